// round 15
// baseline (speedup 1.0000x reference)
#include <cuda_runtime.h>
#include <cstdint>

// AccRNNCell R14: collapsed recurrence (R12) + 2-CTA N-split clusters.
// Cluster = 2 CTAs sharing 8 batch rows; CTA rank r computes N-cols
// [r*256,(r+1)*256) of every stage and DSMEM-broadcasts its half of the new
// state to the peer. Weight reads per CTA halve; FMA per CTA unchanged.
//   ns0 = h0@WA0 + [xt,acc]@WB0 + f0
//   ns1 = h1@WA1 + ns0@E1 + f1
//   ns2 = h2@WA2 + ns1@E2 + f2
//   res = ns2@Eout + fout ; acc += res
// hsT parity-double-buffered so one cluster barrier per stage suffices.

#define UU 512
#define FF 64
#define PP 32
#define BT 8          // batch rows per cluster
#define NH 256        // N-cols per CTA
#define TPB 512
#define NG 4
#define TT 512
#define BB 512

typedef unsigned long long u64;

__device__ float dE1[UU * UU];
__device__ float dE2[UU * UU];
__device__ float dEout[UU * PP];
__device__ float df0[UU];
__device__ float df1[UU];
__device__ float df2[UU];
__device__ float dfout[PP];

// hsT[2][3][UU][BT] + inT[96][BT] + part[NG][NH][BT] + accS + wpart
#define SMEM_FLOATS (2*3*UU*BT + 96*BT + NG*NH*BT + BT*PP + TPB)
#define SMEM_BYTES  (SMEM_FLOATS * 4)

// ---------------- precompute (unchanged from R12) ----------------
__global__ void __launch_bounds__(512) precompute(
    const float* __restrict__ WBr, const float* __restrict__ bBr,
    const float* __restrict__ WC,  const float* __restrict__ bC,
    const float* __restrict__ Wout, const float* __restrict__ bout,
    const float* __restrict__ bA,  const float* __restrict__ bB0)
{
    const int bid = blockIdx.x, tid = threadIdx.x;
    __shared__ float row[UU];
    if (bid < 2 * UU) {
        int w = bid >> 9;
        int r = bid & (UU - 1);
        const float* Wc = WC + (size_t)w * UU * UU + (size_t)r * UU;
        const float* Wb = WBr + (size_t)w * UU * UU;
        float* E = w ? dE2 : dE1;
        row[tid] = Wc[tid];
        __syncthreads();
        float s = 0.f;
        #pragma unroll 8
        for (int m = 0; m < UU; ++m)
            s = fmaf(row[m], Wb[(size_t)m * UU + tid], s);
        E[(size_t)r * UU + tid] = s;
    } else if (bid < 3 * UU) {
        int r = bid - 2 * UU;
        const float* Wc = WC + (size_t)2 * UU * UU + (size_t)r * UU;
        int kg = tid >> 5, p = tid & 31;
        float s = 0.f;
        #pragma unroll 8
        for (int m = kg * 32; m < kg * 32 + 32; ++m)
            s = fmaf(Wc[m], Wout[m * PP + p], s);
        row[tid] = s;
        __syncthreads();
        if (tid < PP) {
            float t = 0.f;
            #pragma unroll
            for (int g = 0; g < 16; ++g) t += row[g * 32 + tid];
            dEout[r * PP + tid] = t;
        }
    } else if (bid == 3 * UU) {
        df0[tid] = bA[tid] + bB0[tid];
    } else if (bid == 3 * UU + 1) {
        float s = bA[UU + tid] + bBr[tid];
        #pragma unroll 8
        for (int m = 0; m < UU; ++m)
            s = fmaf(bC[m], WBr[(size_t)m * UU + tid], s);
        df1[tid] = s;
    } else if (bid == 3 * UU + 2) {
        float s = bA[2 * UU + tid] + bBr[UU + tid];
        #pragma unroll 8
        for (int m = 0; m < UU; ++m)
            s = fmaf(bC[UU + m], WBr[(size_t)UU * UU + (size_t)m * UU + tid], s);
        df2[tid] = s;
    } else {
        if (tid < PP) {
            float s = bout[tid];
            #pragma unroll 8
            for (int m = 0; m < UU; ++m)
                s = fmaf(bC[2 * UU + m], Wout[m * PP + tid], s);
            dfout[tid] = s;
        }
    }
}

// ---------------- device helpers ----------------
__device__ __forceinline__ u64 pack2(float x, float y) {
    u64 v; asm("mov.b64 %0, {%1, %2};" : "=l"(v) : "f"(x), "f"(y)); return v;
}
__device__ __forceinline__ uint32_t smem_u32(const void* p) {
    uint32_t a;
    asm("{ .reg .u64 t; cvta.to.shared.u64 t, %1; cvt.u32.u64 %0, t; }"
        : "=r"(a) : "l"(p));
    return a;
}
__device__ __forceinline__ void st_peer_f4(uint32_t laddr, uint32_t peer, float4 v) {
    uint32_t r;
    asm("mapa.shared::cluster.u32 %0, %1, %2;" : "=r"(r) : "r"(laddr), "r"(peer));
    asm volatile("st.shared::cluster.v4.b32 [%0], {%1,%2,%3,%4};"
                 :: "r"(r), "r"(__float_as_uint(v.x)), "r"(__float_as_uint(v.y)),
                    "r"(__float_as_uint(v.z)), "r"(__float_as_uint(v.w)) : "memory");
}
#define CLUSTER_BAR() do { \
    asm volatile("barrier.cluster.arrive.aligned;" ::: "memory"); \
    asm volatile("barrier.cluster.wait.aligned;"   ::: "memory"); } while (0)

// 2 cols x 8 rows per thread. a[c*4+h] = f32x2 over rows (2h,2h+1), col j0+c.
__device__ __forceinline__ void fma8x(const float2* __restrict__ w,
                                      const float* __restrict__ S,
                                      u64* __restrict__ a)
{
    #pragma unroll
    for (int i = 0; i < 8; ++i) {
        ulonglong2 h01 = *reinterpret_cast<const ulonglong2*>(S + i * BT);
        ulonglong2 h23 = *reinterpret_cast<const ulonglong2*>(S + i * BT + 4);
        u64 w0 = pack2(w[i].x, w[i].x), w1 = pack2(w[i].y, w[i].y);
        asm("fma.rn.f32x2 %0, %1, %2, %0;" : "+l"(a[0]) : "l"(w0), "l"(h01.x));
        asm("fma.rn.f32x2 %0, %1, %2, %0;" : "+l"(a[1]) : "l"(w0), "l"(h01.y));
        asm("fma.rn.f32x2 %0, %1, %2, %0;" : "+l"(a[2]) : "l"(w0), "l"(h23.x));
        asm("fma.rn.f32x2 %0, %1, %2, %0;" : "+l"(a[3]) : "l"(w0), "l"(h23.y));
        asm("fma.rn.f32x2 %0, %1, %2, %0;" : "+l"(a[4]) : "l"(w1), "l"(h01.x));
        asm("fma.rn.f32x2 %0, %1, %2, %0;" : "+l"(a[5]) : "l"(w1), "l"(h01.y));
        asm("fma.rn.f32x2 %0, %1, %2, %0;" : "+l"(a[6]) : "l"(w1), "l"(h23.x));
        asm("fma.rn.f32x2 %0, %1, %2, %0;" : "+l"(a[7]) : "l"(w1), "l"(h23.y));
    }
}
__device__ __forceinline__ void load8w(float2* __restrict__ w, const float* __restrict__ W)
{
    #pragma unroll
    for (int i = 0; i < 8; ++i)
        w[i] = __ldg(reinterpret_cast<const float2*>(W + (size_t)i * UU));
}

template<int K>
__device__ __forceinline__ void gemm_rp(const float* __restrict__ W,   // +kbeg*UU + jcol
                                        const float* __restrict__ S,   // +kbeg*BT
                                        u64* __restrict__ a)
{
    static_assert(K % 16 == 0 && K >= 16, "K must be multiple of 16");
    float2 wa[8], wb[8];
    load8w(wa, W);
    #pragma unroll 2
    for (int k0 = 0; k0 < K - 16; k0 += 16) {
        load8w(wb, W + (size_t)(k0 + 8) * UU);
        fma8x(wa, S + k0 * BT, a);
        load8w(wa, W + (size_t)(k0 + 16) * UU);
        fma8x(wb, S + (k0 + 8) * BT, a);
    }
    load8w(wb, W + (size_t)(K - 8) * UU);
    fma8x(wa, S + (K - 16) * BT, a);
    fma8x(wb, S + (K - 8) * BT, a);
}

__global__ void __launch_bounds__(TPB, 1) __cluster_dims__(2, 1, 1)
accrnn_persistent(const float* __restrict__ x,
                  const float* __restrict__ WA,
                  const float* __restrict__ WB0,
                  float* __restrict__ out)
{
    extern __shared__ float smem[];
    float* hsT   = smem;                       // [2][3][UU][BT]
    float* inT   = hsT + 2 * 3 * UU * BT;      // [96][BT]
    float* part  = inT + 96 * BT;              // [NG][NH][BT]
    float* accS  = part + NG * NH * BT;        // [BT*PP]
    float* wpart = accS + BT * PP;             // [TPB]

    const int tid = threadIdx.x;
    uint32_t rank; asm("mov.u32 %0, %%cluster_ctarank;" : "=r"(rank));
    const uint32_t peer = rank ^ 1u;
    const int b0  = (blockIdx.x >> 1) * BT;
    const int grp = tid >> 7;          // 0..3
    const int ct  = tid & 127;
    const int j0  = (int)rank * NH + ct * 2;   // global weight-col pair

    for (int i = tid; i < 2 * 3 * UU * BT; i += TPB) hsT[i] = 0.f;
    if (tid < BT * PP) accS[tid] = 0.f;
    __syncthreads();
    CLUSTER_BAR();   // both CTAs zeroed before any peer writes

    const int xr = tid >> 6;           // 0..7
    const int xf = tid & 63;
    const float* xrow = x + ((size_t)(b0 + xr) * TT) * FF + xf;

    const int ccol = tid >> 1;         // combine: col 0..255
    const int chalf = (tid & 1) * 4;   // rows 0-3 / 4-7

    for (int t = 0; t < TT; ++t) {
        const int buf = t & 1;
        float* hsNew = hsT + buf * 3 * UU * BT;
        float* hsOld = hsT + (buf ^ 1) * 3 * UU * BT;

        // ---- inT = concat(x_t, acc) (local) ----
        inT[xf * BT + xr] = xrow[(size_t)t * FF];
        if (tid < BT * PP) {
            int r = tid >> 5, p = tid & 31;
            inT[(FF + p) * BT + r] = accS[tid];
        }
        __syncthreads();

        // ======== 3 stages ========
        #pragma unroll
        for (int s = 0; s < 3; ++s) {
            u64 a[8];
            const float* f = (s == 0) ? df0 : (s == 1) ? df1 : df2;
            if (grp == 0) {
                float bb0 = f[j0], bb1 = f[j0 + 1];
                a[0] = a[1] = a[2] = a[3] = pack2(bb0, bb0);
                a[4] = a[5] = a[6] = a[7] = pack2(bb1, bb1);
            } else {
                #pragma unroll
                for (int i = 0; i < 8; ++i) a[i] = 0ull;
            }
            if (s == 0) {
                const float* W0 = WA + j0;
                if (grp < 3) {
                    int kbeg = grp * 160;
                    gemm_rp<160>(W0 + (size_t)kbeg * UU, hsOld + kbeg * BT, a);
                } else {
                    gemm_rp<32>(W0 + (size_t)480 * UU, hsOld + 480 * BT, a);
                    gemm_rp<96>(WB0 + j0, inT, a);
                }
            } else {
                if (grp < 2) {
                    int kbeg = grp * 256;
                    gemm_rp<256>(WA + (size_t)s * UU * UU + (size_t)kbeg * UU + j0,
                                 hsOld + s * UU * BT + kbeg * BT, a);
                } else {
                    const float* E = (s == 1) ? dE1 : dE2;
                    int kbeg = (grp - 2) * 256;
                    gemm_rp<256>(E + (size_t)kbeg * UU + j0,
                                 hsNew + (s - 1) * UU * BT + kbeg * BT, a);
                }
            }
            {   // part[grp][ct*2 .. +1][0..7]
                float* pp = part + grp * NH * BT + (ct * 2) * BT;
                ulonglong2 v;
                v.x = a[0]; v.y = a[1];
                *reinterpret_cast<ulonglong2*>(pp) = v;          // col0 rows0-3
                v.x = a[2]; v.y = a[3];
                *reinterpret_cast<ulonglong2*>(pp + 4) = v;      // col0 rows4-7
                v.x = a[4]; v.y = a[5];
                *reinterpret_cast<ulonglong2*>(pp + BT) = v;     // col1 rows0-3
                v.x = a[6]; v.y = a[7];
                *reinterpret_cast<ulonglong2*>(pp + BT + 4) = v; // col1 rows4-7
            }
            __syncthreads();
            {   // combine + broadcast to peer
                const float* base = part + ccol * BT + chalf;
                float4 sv = *reinterpret_cast<const float4*>(base);
                #pragma unroll
                for (int g = 1; g < NG; ++g) {
                    float4 q = *reinterpret_cast<const float4*>(base + g * NH * BT);
                    sv.x += q.x; sv.y += q.y; sv.z += q.z; sv.w += q.w;
                }
                float* dst = hsNew + s * UU * BT + ((int)rank * NH + ccol) * BT + chalf;
                *reinterpret_cast<float4*>(dst) = sv;
                st_peer_f4(smem_u32(dst), peer, sv);
            }
            CLUSTER_BAR();   // peer half visible before next stage reads
        }

        // ======== out: res = ns2 @ Eout + fout ; acc += res ========
        {
            int ks = tid >> 8;                 // 0/1 k-split
            int rp = tid & 255;
            int r = rp >> 5, p = rp & 31;
            const float* n2 = hsNew + 2 * UU * BT;
            float sv = 0.f;
            int kbeg = ks * 256;
            #pragma unroll 8
            for (int k = kbeg; k < kbeg + 256; ++k)
                sv = fmaf(n2[k * BT + r], dEout[k * PP + p], sv);
            wpart[tid] = sv;
        }
        __syncthreads();
        if (tid < BT * PP) {
            int r = tid >> 5, p = tid & 31;
            float tot = wpart[tid] + wpart[tid + 256] + dfout[p];
            accS[tid] += tot;
            if ((uint32_t)(r >> 2) == rank)
                out[((size_t)(b0 + r) * TT + t) * PP + p] = tot;
        }
        __syncthreads();
    }
}

extern "C" void kernel_launch(void* const* d_in, const int* in_sizes, int n_in,
                              void* d_out, int out_size)
{
    const float* x    = (const float*)d_in[0];
    const float* WA   = (const float*)d_in[1];
    const float* bA   = (const float*)d_in[2];
    const float* WB0  = (const float*)d_in[3];
    const float* bB0  = (const float*)d_in[4];
    const float* WBr  = (const float*)d_in[5];
    const float* bBr  = (const float*)d_in[6];
    const float* WC   = (const float*)d_in[7];
    const float* bC   = (const float*)d_in[8];
    const float* Wout = (const float*)d_in[9];
    const float* bout = (const float*)d_in[10];
    float* out = (float*)d_out;

    precompute<<<3 * UU + 4, 512>>>(WBr, bBr, WC, bC, Wout, bout, bA, bB0);

    cudaFuncSetAttribute(accrnn_persistent,
                         cudaFuncAttributeMaxDynamicSharedMemorySize, SMEM_BYTES);
    accrnn_persistent<<<BB / BT * 2, TPB, SMEM_BYTES>>>(x, WA, WB0, out);
}